// round 17
// baseline (speedup 1.0000x reference)
#include <cuda_runtime.h>
#include <cuda_bf16.h>
#include <cstdint>

// act_shift = log(1/(1-1e-4) - 1) in double, narrowed (matches numpy path).
#define ACT_SHIFT (-9.210240366976184)
#define LOG2E_D   (1.4426950408889634)

// Single-instruction MUFU paths.
__device__ __forceinline__ float ex2f(float x) {
    float r; asm("ex2.approx.ftz.f32 %0, %1;" : "=f"(r) : "f"(x)); return r;
}
__device__ __forceinline__ float rsqf(float x) {
    float r; asm("rsqrt.approx.ftz.f32 %0, %1;" : "=f"(r) : "f"(x)); return r;
}

// alpha = 1-(1+y)^{-1/2} = y*(1/2 - 3/8 y + 5/16 y^2 - 35/128 y^3 + 63/256 y^4)
__device__ __forceinline__ float alpha_poly(float y) {
    return y * fmaf(y, fmaf(y, fmaf(y, fmaf(y, 0.24609375f, -0.2734375f),
                                    0.3125f), -0.375f), 0.5f);
}

// ---------------------------------------------------------------------------
// Fused kernel: one warp per ray.
// Prologue: warp-cooperative DUAL lower_bound — lanes 0..15 search key=w,
// lanes 16..31 search key=w+1. 16 probes/round via one ballot -> range/16 per
// round -> ~6 dependent rounds (vs 23 thread-serial), at full occupancy.
// Then: the proven 160-element-tile product-domain segmented scan.
// ---------------------------------------------------------------------------
__global__ void __launch_bounds__(256)
fused_ray_kernel(const float* __restrict__ density,
                 const int* __restrict__ ray_id,
                 float* __restrict__ out_w,
                 float* __restrict__ out_ainv,
                 int Nrays, int M) {
    int warp_id = (int)((blockIdx.x * (unsigned)blockDim.x + threadIdx.x) >> 5);
    int lane    = threadIdx.x & 31;
    if (warp_id >= Nrays) return;          // warp-uniform

    // ---- cooperative 16+16 dual binary search ----
    int h   = lane >> 4;                    // 0: key=w, 1: key=w+1
    int s   = lane & 15;
    int key = warp_id + h;                  // all ids < Nrays -> lb(Nrays)=M ok
    int lo = 0, hi = M;                     // invariant: a[lo-1] < key <= a[hi]

    while (__any_sync(0xFFFFFFFFu, hi - lo > 0)) {
        int range = hi - lo;
        int chunk = (range + 15) >> 4;      // 0 only when range==0 (inactive)
        int p  = lo + s * chunk;
        int pc = (p < M) ? p : (M - 1);     // safe index
        bool pred = (p < hi) && (__ldg(ray_id + pc) < key);
        unsigned bal  = __ballot_sync(0xFFFFFFFFu, pred);
        int c = __popc((bal >> (h << 4)) & 0xFFFFu);
        if (range > 0) {
            int nlo = (c == 0) ? lo : lo + (c - 1) * chunk + 1;
            int nhi = hi;
            if (c < 16) { int ph = lo + c * chunk; nhi = (ph < hi) ? ph : hi; }
            lo = nlo; hi = nhi;
        }
    }
    int start = __shfl_sync(0xFFFFFFFFu, lo, 0);
    int end   = __shfl_sync(0xFFFFFFFFu, lo, 16);

    // ---- proven 160-element-tile product-domain scan (round-12 body) ----
    const float l2e  = (float)LOG2E_D;
    const float sl2e = (float)(ACT_SHIFT * LOG2E_D);

    int astart = start & ~3;                // 4-aligned tile origin
    int plo    = start - astart;            // 0..3 head pad (lane 0)
    float carry = 1.0f;                     // running product of q = 1+y

    for (int abase = astart; abase < end; abase += 160) {
        // ---- Part 1: [abase, abase+128), 4/lane vectorized ----
        int i0 = abase + lane * 4;          // 4-aligned (160 % 4 == 0)
        int hi1 = end - i0;                 // j valid iff j < hi1

        float d0 = 0.f, d1 = 0.f, d2 = 0.f, d3 = 0.f;
        if (i0 + 3 < M) {
            float4 v4 = *reinterpret_cast<const float4*>(density + i0);
            d0 = v4.x; d1 = v4.y; d2 = v4.z; d3 = v4.w;
        } else {
            if (i0     < M) d0 = density[i0];
            if (i0 + 1 < M) d1 = density[i0 + 1];
            if (i0 + 2 < M) d2 = density[i0 + 2];
            if (i0 + 3 < M) d3 = density[i0 + 3];
        }

        float y0 = (0 < hi1) ? ex2f(fmaf(d0, l2e, sl2e)) : 0.0f;
        float y1 = (1 < hi1) ? ex2f(fmaf(d1, l2e, sl2e)) : 0.0f;
        float y2 = (2 < hi1) ? ex2f(fmaf(d2, l2e, sl2e)) : 0.0f;
        float y3 = (3 < hi1) ? ex2f(fmaf(d3, l2e, sl2e)) : 0.0f;

        if (abase == astart && lane == 0) { // head-alignment pad
            if (plo > 0) y0 = 0.0f;
            if (plo > 1) y1 = 0.0f;
            if (plo > 2) y2 = 0.0f;
        }

        float q0 = 1.0f + y0, q1 = 1.0f + y1, q2 = 1.0f + y2, q3 = 1.0f + y3;
        float P0 = q0;
        float P1 = P0 * q1;
        float P2 = P1 * q2;
        float P3 = P2 * q3;

        float v = P3;                       // warp product scan
        #pragma unroll
        for (int o = 1; o < 32; o <<= 1) {
            float u = __shfl_up_sync(0xFFFFFFFFu, v, o);
            if (lane >= o) v *= u;
        }
        float ve = __shfl_up_sync(0xFFFFFFFFu, v, 1);
        if (lane == 0) ve = 1.0f;
        float P128 = __shfl_sync(0xFFFFFFFFu, v, 31);

        float T = rsqf(carry * ve);

        float a0 = alpha_poly(y0);
        float a1 = alpha_poly(y1);
        float a2 = alpha_poly(y2);
        float a3 = alpha_poly(y3);

        float w0 = a0 * T;  T = fmaf(-T, a0, T);
        float w1 = a1 * T;  T = fmaf(-T, a1, T);
        float w2 = a2 * T;  T = fmaf(-T, a2, T);
        float w3 = a3 * T;

        if (i0 >= start && i0 + 4 <= end) { // interior quad (common)
            *reinterpret_cast<float4*>(out_w + i0) = make_float4(w0, w1, w2, w3);
        } else {
            if (i0     >= start && 0 < hi1) out_w[i0]     = w0;
            if (i0 + 1 >= start && 1 < hi1) out_w[i0 + 1] = w1;
            if (i0 + 2 >= start && 2 < hi1) out_w[i0 + 2] = w2;
            if (i0 + 3 >= start && 3 < hi1) out_w[i0 + 3] = w3;
        }

        carry *= P128;                      // product up to abase+128

        // ---- Part 2: [abase+128, abase+160) — warp-uniform skip ----
        if (abase + 128 < end) {
            int i2 = abase + 128 + lane;    // i2 > start always
            bool v2ok = (i2 < end);
            float d4 = 0.0f;
            if (v2ok) d4 = density[i2];     // coalesced 32-wide
            float y4 = v2ok ? ex2f(fmaf(d4, l2e, sl2e)) : 0.0f;
            float q4 = 1.0f + y4;

            float s2 = q4;                  // second warp product scan
            #pragma unroll
            for (int o = 1; o < 32; o <<= 1) {
                float u = __shfl_up_sync(0xFFFFFFFFu, s2, o);
                if (lane >= o) s2 *= u;
            }
            float ve2 = __shfl_up_sync(0xFFFFFFFFu, s2, 1);
            if (lane == 0) ve2 = 1.0f;

            float T2 = rsqf(carry * ve2);
            float w4 = alpha_poly(y4) * T2;
            if (v2ok) out_w[i2] = w4;

            carry *= __shfl_sync(0xFFFFFFFFu, s2, 31);
        }
    }

    if (lane == 0) {
        out_ainv[warp_id] = rsqf(carry);    // empty ray: carry==1 -> 1
    }
}

extern "C" void kernel_launch(void* const* d_in, const int* in_sizes, int n_in,
                              void* d_out, int out_size) {
    const float* density = (const float*)d_in[0];
    const int*   ray_id  = (const int*)d_in[1];
    int M = in_sizes[0];
    int Nrays = out_size - M;            // output = [weights(M) | alphainv_last(N)]
    if (Nrays < 0) Nrays = 0;

    float* out_w    = (float*)d_out;
    float* out_ainv = (float*)d_out + M;

    if (Nrays > 0) {
        int threads = 256;               // 8 warps/block -> 8 rays/block
        long long total_threads = (long long)Nrays * 32;
        int blocks = (int)((total_threads + threads - 1) / threads);
        fused_ray_kernel<<<blocks, threads>>>(density, ray_id, out_w, out_ainv,
                                              Nrays, M);
    }
}